// round 5
// baseline (speedup 1.0000x reference)
#include <cuda_runtime.h>

// LR_23029614641373: logit = W[u] + W[6040+m] + b; out = [1-p, p]
// B = 4,194,304. W (9923 floats) staged in SMEM, pre-scaled by 0.5.
// p = 0.5 + 0.5*tanh(l/2) via MUFU tanh.approx.
// R2's software-pipelined grid-stride loop (next int4 load issued before
// the dependent LDS/MUFU chain) — this structure measured 3us faster than
// the compiler's MLP=1 loop in R4.

#define N_USERS  6040
#define TABLE    9923
#define NTHREADS 512
#define NBLK_SM  4

__device__ __forceinline__ float tanh_fast(float x) {
    float y;
    asm("tanh.approx.f32 %0, %1;" : "=f"(y) : "f"(x));
    return y;
}

__global__ void __launch_bounds__(NTHREADS, NBLK_SM) lr_smem_kernel(
    const int4* __restrict__ x2,      // [n2] two (u,m) rows per int4
    const float* __restrict__ w,      // [9923]
    const float* __restrict__ bptr,   // [1]
    float4* __restrict__ out,         // [n2] {1-p0,p0,1-p1,p1}
    int n2)
{
    __shared__ float sw[TABLE];       // holds 0.5*W
    for (int i = threadIdx.x; i < TABLE; i += NTHREADS)
        sw[i] = 0.5f * w[i];
    __syncthreads();

    const float hbias = 0.5f * __ldg(bptr);
    const int stride = gridDim.x * blockDim.x;
    int i = blockIdx.x * blockDim.x + threadIdx.x;

    if (i >= n2) return;

    // software pipeline: keep the next int4 load in flight while the
    // current LDS->tanh->store chain executes
    int4 v = x2[i];
    int inext = i + stride;
    while (true) {
        int4 vn;
        bool has_next = (inext < n2);
        if (has_next) vn = x2[inext];

        float h0 = sw[v.x] + sw[N_USERS + v.y] + hbias;  // h = l/2
        float h1 = sw[v.z] + sw[N_USERS + v.w] + hbias;
        float t0 = tanh_fast(h0);
        float t1 = tanh_fast(h1);

        out[i] = make_float4(fmaf(-0.5f, t0, 0.5f), fmaf(0.5f, t0, 0.5f),
                             fmaf(-0.5f, t1, 0.5f), fmaf(0.5f, t1, 0.5f));

        if (!has_next) break;
        i = inext;
        inext += stride;
        v = vn;
    }
}

// Rare odd-row tail (B is even in this dataset).
__global__ void lr_tail_kernel(
    const int2* __restrict__ x,
    const float* __restrict__ w,
    const float* __restrict__ bptr,
    float2* __restrict__ out,
    int start, int n)
{
    int i = start + blockIdx.x * blockDim.x + threadIdx.x;
    if (i >= n) return;
    int2 v = x[i];
    float h = 0.5f * (__ldg(w + v.x) + __ldg(w + N_USERS + v.y) + __ldg(bptr));
    float t = tanh_fast(h);
    out[i] = make_float2(fmaf(-0.5f, t, 0.5f), fmaf(0.5f, t, 0.5f));
}

extern "C" void kernel_launch(void* const* d_in, const int* in_sizes, int n_in,
                              void* d_out, int out_size)
{
    const int*   x = (const int*)d_in[0];     // [B, 2] int32
    const float* W = (const float*)d_in[1];   // [1, 9923]
    const float* b = (const float*)d_in[2];   // [1]
    float* out = (float*)d_out;               // [B, 2]

    int B  = in_sizes[0] / 2;   // rows
    int n2 = B / 2;             // int4 groups (2 rows each)

    if (n2 > 0) {
        int max_blocks = 148 * NBLK_SM;
        int blocks = (n2 + NTHREADS - 1) / NTHREADS;
        if (blocks > max_blocks) blocks = max_blocks;
        lr_smem_kernel<<<blocks, NTHREADS>>>(
            (const int4*)x, W, b, (float4*)out, n2);
    }
    if (B & 1) {
        lr_tail_kernel<<<1, 32>>>(
            (const int2*)x, W, b, (float2*)out, 2 * n2, B);
    }
}